// round 5
// baseline (speedup 1.0000x reference)
#include <cuda_runtime.h>
#include <cuda_bf16.h>

// firing_model: next = -prev + tanh(prev @ x) from prev = 0 -> identically
// zero trajectory (tanh(0) = 0 exactly in fp32). Output [499800, 69] is all
// zeros -> pure 138 MB zero-fill of d_out. HBM-write bound (~6.9 TB/s
// achieved; ~7 TB/s effective ceiling).
//
// R5: final probe — 256-bit streaming stores (st.global.cs.v8.f32,
// sm_100a+). Same exact-cover 16 KB/block geometry as R4, half the STG
// instructions: shorter per-warp store pipeline, quicker block drain.

#define FILL_THREADS 256
#define V8_PER_THREAD 2   // 2 x 32B per thread -> block covers 16 KB

__device__ __forceinline__ void st_zero_v8_cs(float* p) {
#if defined(__CUDA_ARCH__) && (__CUDA_ARCH__ >= 1000)
    asm volatile(
        "st.global.cs.v8.f32 [%0], {%1, %1, %1, %1, %1, %1, %1, %1};"
        :: "l"(p), "f"(0.0f) : "memory");
#else
    float4 z = make_float4(0.0f, 0.0f, 0.0f, 0.0f);
    __stcs((float4*)p, z);
    __stcs((float4*)p + 1, z);
#endif
}

__global__ void __launch_bounds__(FILL_THREADS)
firing_model_zero_fill_v8(float* __restrict__ out, long long n8) {
    // n8 = number of 8-float (32B) chunks
    long long base = (long long)blockIdx.x * (FILL_THREADS * V8_PER_THREAD)
                   + threadIdx.x;
#pragma unroll
    for (int k = 0; k < V8_PER_THREAD; k++) {
        long long i = base + (long long)k * FILL_THREADS;
        if (i < n8) st_zero_v8_cs(out + i * 8);
    }
}

__global__ void firing_model_zero_fill_tail(float* __restrict__ out,
                                            long long start, long long n) {
    long long i = start + (long long)blockIdx.x * blockDim.x + threadIdx.x;
    if (i < n) {
        out[i] = 0.0f;
    }
}

extern "C" void kernel_launch(void* const* d_in, const int* in_sizes, int n_in,
                              void* d_out, int out_size) {
    (void)d_in; (void)in_sizes; (void)n_in;

    float* out = (float*)d_out;
    long long n  = (long long)out_size;   // 34,486,200 floats expected
    long long n8 = n >> 3;                // 32B chunks: 4,310,775
    long long tail_start = n8 << 3;       // 34,486,200 -> no tail for this shape

    if (n8 > 0) {
        long long per_block = FILL_THREADS * V8_PER_THREAD;
        long long blocks = (n8 + per_block - 1) / per_block;   // ~8,420
        firing_model_zero_fill_v8<<<(unsigned int)blocks, FILL_THREADS>>>(
            out, n8);
    }
    if (tail_start < n) {  // defensive for other shapes
        long long tail = n - tail_start;
        int blocks = (int)((tail + 255) / 256);
        firing_model_zero_fill_tail<<<blocks, 256>>>(out, tail_start, n);
    }
}